// round 3
// baseline (speedup 1.0000x reference)
#include <cuda_runtime.h>
#include <cuda_pipeline.h>

// ---------------- problem dims (fixed by the dataset) ----------------
#define BATCH   2
#define C_IN    256
#define HH      40
#define WW      40
#define CMID    64     // compressed channels
#define CK      100    // k2 * S^2 encoder output channels
#define KK      25     // k2
#define HPAD    44     // xT padded (halo 2)
#define CPH     42     // comp padded (halo 1)

typedef unsigned long long u64;

__device__ __forceinline__ u64 dup2f(float x) {
    u64 r; asm("mov.b64 %0,{%1,%1};" : "=l"(r) : "f"(x)); return r;
}
__device__ __forceinline__ void fma2(u64& d, u64 a, u64 b) {
    asm("fma.rn.f32x2 %0,%1,%2,%0;" : "+l"(d) : "l"(a), "l"(b));
}

// ---------------- scratch (zero-initialized at module load; halos stay 0) ----------------
__device__ __align__(16) float g_xT  [BATCH * HPAD * HPAD * C_IN];   // x NHWC, 2-px zero halo
__device__ __align__(16) float g_comp[BATCH * CPH  * CPH  * CMID];   // compressed NHWC, 1-px halo
__device__ __align__(16) float g_kern[BATCH * HH * WW * CK];         // encoder conv out, NHWC
__device__ __align__(16) float g_wt  [9 * CMID * CK];                // w_enc transposed [tap][ci][o]
__device__ __align__(16) float4 g_wX [ (C_IN/2) * (CMID/2) ];        // w_comp interleaved [c2][opair]

// ---------------- prep: weight reshapes ----------------
// g_wX[c2*32 + l] = { w(2l,2c2), w(2l+1,2c2), w(2l,2c2+1), w(2l+1,2c2+1) }  (w = wcomp[o][c])
// g_wt[tap][ci][o] = wenc[o][ci][tap]
__global__ void prep_kernel(const float* __restrict__ wcomp,
                            const float* __restrict__ wenc) {
    int i = blockIdx.x * 256 + threadIdx.x;
    if (i < 4096) {
        int c2 = i >> 5, l = i & 31;
        const float* w0 = wcomp + (2 * l) * C_IN + 2 * c2;
        const float* w1 = w0 + C_IN;
        g_wX[i] = make_float4(w0[0], w1[0], w0[1], w1[1]);
    }
    int j = i - 4096;
    if (j >= 0 && j < 9 * CMID * CK) {
        int tap  = j / (CMID * CK);
        int rest = j % (CMID * CK);
        int ci   = rest / CK;
        int o    = rest % CK;
        g_wt[j] = wenc[o * (CMID * 9) + ci * 9 + tap];
    }
}

// ---------------- stage A: streaming 1x1 GEMM (blocks 0..199) + x transpose (blocks 200..599) ----
// GEMM: warp = 4 px x 64 outputs. No smem, no syncs. x read directly from NCHW.
__global__ void __launch_bounds__(128) stageA_compress(const float* __restrict__ x) {
    __shared__ float s[64 * 33];
    const int t   = threadIdx.x;
    const int blk = blockIdx.x;

    if (blk < 200) {
        const int wid = t >> 5, l = t & 31;
        const int g = blk * 16 + wid * 4;        // global pixel (incl batch)
        const int b = g / (HH * WW), p = g % (HH * WW);

        const float* xp = x + (size_t)b * C_IN * (HH * WW) + p;
        const ulonglong2* wp = (const ulonglong2*)g_wX + l;

        u64 acc0 = 0, acc1 = 0, acc2 = 0, acc3 = 0;
        #pragma unroll 2
        for (int k = 0; k < 64; k++) {           // 4 channels per iter
            float4 x0 = *(const float4*)(xp);
            float4 x1 = *(const float4*)(xp + 1600);
            float4 x2 = *(const float4*)(xp + 3200);
            float4 x3 = *(const float4*)(xp + 4800);
            ulonglong2 wA = wp[0];               // c, c+1
            ulonglong2 wB = wp[32];              // c+2, c+3
            fma2(acc0, dup2f(x0.x), wA.x); fma2(acc1, dup2f(x0.y), wA.x);
            fma2(acc2, dup2f(x0.z), wA.x); fma2(acc3, dup2f(x0.w), wA.x);
            fma2(acc0, dup2f(x1.x), wA.y); fma2(acc1, dup2f(x1.y), wA.y);
            fma2(acc2, dup2f(x1.z), wA.y); fma2(acc3, dup2f(x1.w), wA.y);
            fma2(acc0, dup2f(x2.x), wB.x); fma2(acc1, dup2f(x2.y), wB.x);
            fma2(acc2, dup2f(x2.z), wB.x); fma2(acc3, dup2f(x2.w), wB.x);
            fma2(acc0, dup2f(x3.x), wB.y); fma2(acc1, dup2f(x3.y), wB.y);
            fma2(acc2, dup2f(x3.z), wB.y); fma2(acc3, dup2f(x3.w), wB.y);
            xp += 6400;
            wp += 64;
        }
        const int hs = p / WW, ws = p % WW;      // 4 px share the row (p % 4 == 0)
        float* dst = &g_comp[((size_t)(b * CPH + hs + 1) * CPH + (ws + 1)) * CMID + 2 * l];
        *(u64*)(dst)           = acc0;
        *(u64*)(dst + CMID)    = acc1;
        *(u64*)(dst + 2*CMID)  = acc2;
        *(u64*)(dst + 3*CMID)  = acc3;
    } else {
        // x transpose: 32 px x 64 c tile via smem
        const int tb  = blk - 200;
        const int pg  = (tb % 100) * 32;         // global pixel (incl batch), 32-aligned
        const int c0  = (tb / 100) * 64;
        const int b   = pg / (HH * WW);
        const int p0  = pg % (HH * WW);
        #pragma unroll
        for (int r = 0; r < 16; r++) {
            int idx = t + r * 128;
            int cl = idx >> 5, pl = idx & 31;
            s[cl * 33 + pl] = x[((size_t)(b * C_IN) + c0 + cl) * (HH * WW) + p0 + pl];
        }
        __syncthreads();
        #pragma unroll
        for (int r = 0; r < 16; r++) {
            int idx = t + r * 128;
            int pl = idx >> 6, cl = idx & 63;
            int px = p0 + pl;
            int hs = px / WW, ws = px % WW;
            g_xT[((size_t)(b * HPAD + hs + 2) * HPAD + (ws + 2)) * C_IN + c0 + cl] =
                s[cl * 33 + pl];
        }
    }
}

// ---------------- stage B: 3x3 encoder conv (64 -> 100 ch) ----------------
#define CS_STRIDE 66
#define B_WBUF    (CMID * CK)                 // 6400 floats per tap
#define SMEM_B_BYTES ((2 * B_WBUF + 48 * CS_STRIDE) * (int)sizeof(float))

__global__ void __launch_bounds__(128) stageB_encoder() {
    extern __shared__ float smB[];
    float* wbuf   = smB;                       // [2][6400]
    float* comp_s = smB + 2 * B_WBUF;          // [48 px][66]

    const int t   = threadIdx.x;
    const int blk = blockIdx.x;
    const int b   = blk / 80;
    const int rem = blk % 80;
    const int h0  = (rem / 4) * 2;
    const int ws0 = (rem % 4) * 10;

    for (int i = t; i < 48 * CMID; i += 128) {
        int pxl = i >> 6, ci = i & 63;
        comp_s[pxl * CS_STRIDE + ci] =
            g_comp[((size_t)(b * CPH + h0 + pxl / 12) * CPH + ws0 + pxl % 12) * CMID + ci];
    }

    for (int i = t; i < B_WBUF / 4; i += 128)
        __pipeline_memcpy_async(&wbuf[i * 4], &g_wt[i * 4], 16);
    __pipeline_commit();

    const int og  = t / 5;          // 0..24 (t<125 active)
    const int pxg = t % 5;
    const bool active = (t < 125);

    u64 a00 = 0, a01 = 0, a10 = 0, a11 = 0;
    u64 b00 = 0, b01 = 0, b10 = 0, b11 = 0;

    for (int tap = 0; tap < 9; tap++) {
        if (tap < 8) {
            float* dst = &wbuf[((tap + 1) & 1) * B_WBUF];
            const float* src = &g_wt[(tap + 1) * B_WBUF];
            for (int i = t; i < B_WBUF / 4; i += 128)
                __pipeline_memcpy_async(&dst[i * 4], &src[i * 4], 16);
            __pipeline_commit();
            __pipeline_wait_prior(1);
        } else {
            __pipeline_wait_prior(0);
        }
        __syncthreads();

        if (active) {
            const float* ws = &wbuf[(tap & 1) * B_WBUF];
            const int dh = tap / 3, dw = tap % 3;
            const float* p00 = &comp_s[(dh * 12 + 2 * pxg + dw) * CS_STRIDE];
            const float* p01 = p00 + CS_STRIDE;
            const float* p10 = p00 + 12 * CS_STRIDE;
            const float* p11 = p10 + CS_STRIDE;
            #pragma unroll 8
            for (int ci = 0; ci < CMID; ci += 2) {
                float2 x00 = *(const float2*)&p00[ci];
                float2 x01 = *(const float2*)&p01[ci];
                float2 x10 = *(const float2*)&p10[ci];
                float2 x11 = *(const float2*)&p11[ci];
                ulonglong2 w0 = *(const ulonglong2*)&ws[ci * CK + og * 4];
                ulonglong2 w1 = *(const ulonglong2*)&ws[(ci + 1) * CK + og * 4];
                u64 d;
                d = dup2f(x00.x); fma2(a00, d, w0.x); fma2(a01, d, w0.y);
                d = dup2f(x01.x); fma2(a10, d, w0.x); fma2(a11, d, w0.y);
                d = dup2f(x10.x); fma2(b00, d, w0.x); fma2(b01, d, w0.y);
                d = dup2f(x11.x); fma2(b10, d, w0.x); fma2(b11, d, w0.y);
                d = dup2f(x00.y); fma2(a00, d, w1.x); fma2(a01, d, w1.y);
                d = dup2f(x01.y); fma2(a10, d, w1.x); fma2(a11, d, w1.y);
                d = dup2f(x10.y); fma2(b00, d, w1.x); fma2(b01, d, w1.y);
                d = dup2f(x11.y); fma2(b10, d, w1.x); fma2(b11, d, w1.y);
            }
        }
        __syncthreads();
    }

    if (active) {
        const int c0 = ws0 + 2 * pxg;
        float* r0 = &g_kern[((size_t)(b * HH + h0) * WW + c0) * CK + og * 4];
        float* r1 = &g_kern[((size_t)(b * HH + h0 + 1) * WW + c0) * CK + og * 4];
        *(ulonglong2*)(r0)      = make_ulonglong2(a00, a01);
        *(ulonglong2*)(r0 + CK) = make_ulonglong2(a10, a11);
        *(ulonglong2*)(r1)      = make_ulonglong2(b00, b01);
        *(ulonglong2*)(r1 + CK) = make_ulonglong2(b10, b11);
    }
}

// ---------------- stage C: pixel-shuffle + softmax + reassembly ----------------
__global__ void __launch_bounds__(256, 2) stageC_reassemble(float* __restrict__ out) {
    __shared__ float4 sk[2][KK];

    const int t   = threadIdx.x;
    const int blk = blockIdx.x;
    const int b   = blk / 800;
    const int q   = blk % 800;

    const int wid = t >> 5, lane = t & 31;
    {
        const int px = wid >> 2, d = wid & 3;
        const int p  = 2 * q + px;
        const int hu = p / 20, pm20 = p % 20;
        const int hc = hu >> 1, sh = hu & 1;
        const int wc = 2 * pm20 + (d >> 1), sw = d & 1;
        float v = -3.0e38f;
        if (lane < KK)
            v = g_kern[((size_t)(b * HH + hc) * WW + wc) * CK + lane * 4 + sh * 2 + sw];
        float m = v;
        #pragma unroll
        for (int off = 16; off; off >>= 1)
            m = fmaxf(m, __shfl_xor_sync(0xffffffffu, m, off));
        float e = (lane < KK) ? __expf(v - m) : 0.f;
        float s = e;
        #pragma unroll
        for (int off = 16; off; off >>= 1)
            s += __shfl_xor_sync(0xffffffffu, s, off);
        if (lane < KK)
            ((float*)&sk[px][lane])[d] = e / s;
    }
    __syncthreads();

    const int half = t >> 7;
    const int ch2  = t & 127;
    const int p    = 2 * q + half;
    const int hsrc = p / WW, wsrc = p % WW;
    const int hu   = p / 20;
    const int wu0  = (p % 20) * 4;

    const float2* xb = (const float2*)
        &g_xT[((size_t)(b * HPAD + hsrc) * HPAD + wsrc) * C_IN + ch2 * 2];
    const ulonglong2* skp = (const ulonglong2*)&sk[half][0];

    u64 a0 = 0, a1 = 0, a2 = 0, a3 = 0;
    #pragma unroll
    for (int ki = 0; ki < 5; ki++) {
        #pragma unroll
        for (int kj = 0; kj < 5; kj++) {
            float2 xv = xb[(ki * HPAD + kj) * (C_IN / 2)];
            ulonglong2 w = skp[ki * 5 + kj];
            u64 x0 = dup2f(xv.x), x1 = dup2f(xv.y);
            fma2(a0, x0, w.x); fma2(a1, x0, w.y);
            fma2(a2, x1, w.x); fma2(a3, x1, w.y);
        }
    }
    const int ch = ch2 * 2;
    float* d0 = out + ((size_t)(b * C_IN + ch) * (2 * HH) + hu) * (2 * WW) + wu0;
    *(ulonglong2*)d0          = make_ulonglong2(a0, a1);
    *(ulonglong2*)(d0 + 6400) = make_ulonglong2(a2, a3);
}

// ---------------- launch ----------------
extern "C" void kernel_launch(void* const* d_in, const int* in_sizes, int n_in,
                              void* d_out, int out_size) {
    const float* x     = (const float*)d_in[0];
    const float* wcomp = (const float*)d_in[1];
    const float* wenc  = (const float*)d_in[2];
    float* out = (float*)d_out;

    cudaFuncSetAttribute(stageB_encoder,
                         cudaFuncAttributeMaxDynamicSharedMemorySize, SMEM_B_BYTES);

    prep_kernel<<<(4096 + 9 * CMID * CK + 255) / 256, 256>>>(wcomp, wenc);
    stageA_compress<<<600, 128>>>(x);
    stageB_encoder<<<160, 128, SMEM_B_BYTES>>>();
    stageC_reassemble<<<BATCH * 800, 256>>>(out);
}

// round 4
// speedup vs baseline: 1.3560x; 1.3560x over previous
#include <cuda_runtime.h>
#include <cuda_pipeline.h>

// ---------------- problem dims (fixed by the dataset) ----------------
#define BATCH   2
#define C_IN    256
#define HH      40
#define WW      40
#define CMID    64     // compressed channels
#define CK      100    // k2 * S^2 encoder output channels
#define KK      25     // k2
#define HPAD    44     // xT padded (halo 2)
#define CPH     42     // comp padded (halo 1)

typedef unsigned long long u64;

__device__ __forceinline__ u64 dup2f(float x) {
    u64 r; asm("mov.b64 %0,{%1,%1};" : "=l"(r) : "f"(x)); return r;
}
__device__ __forceinline__ void fma2(u64& d, u64 a, u64 b) {
    asm("fma.rn.f32x2 %0,%1,%2,%0;" : "+l"(d) : "l"(a), "l"(b));
}

// ---------------- scratch (zero-initialized at module load; halos stay 0) ----------------
__device__ __align__(16) float g_xT  [BATCH * HPAD * HPAD * C_IN];   // x NHWC, 2-px zero halo
__device__ __align__(16) float g_comp[BATCH * CPH  * CPH  * CMID];   // compressed NHWC, 1-px halo
__device__ __align__(16) float g_kern[BATCH * HH * WW * CK];         // encoder conv out, NHWC
__device__ __align__(16) float g_wt  [9 * CMID * CK];                // w_enc transposed [tap][ci][o]
__device__ __align__(16) float g_wc  [C_IN * CMID];                  // w_comp transposed [c][o]

// ---------------- prep: weight transposes ----------------
__global__ void prep_kernel(const float* __restrict__ wcomp,
                            const float* __restrict__ wenc) {
    int i = blockIdx.x * 256 + threadIdx.x;
    if (i < C_IN * CMID) {                    // g_wc[c][o] = wcomp[o][c]
        int c = i >> 6, o = i & 63;
        g_wc[i] = wcomp[o * C_IN + c];
    }
    int j = i - C_IN * CMID;
    if (j >= 0 && j < 9 * CMID * CK) {        // g_wt[tap][ci][o] = wenc[o][ci][tap]
        int tap  = j / (CMID * CK);
        int rest = j % (CMID * CK);
        int ci   = rest / CK;
        int o    = rest % CK;
        g_wt[j] = wenc[o * (CMID * 9) + ci * 9 + tap];
    }
}

// ---------------- x transpose: NCHW -> padded NHWC (g_xT) ----------------
// 400 blocks x 128 threads: 32 px x 64 ch tiles through smem.
__global__ void __launch_bounds__(128) xpose_kernel(const float* __restrict__ x) {
    __shared__ float s[64 * 33];
    const int t  = threadIdx.x;
    const int tb = blockIdx.x;
    const int pg = (tb % 100) * 32;           // global pixel (incl batch), 32-aligned
    const int c0 = (tb / 100) * 64;
    const int b  = pg / (HH * WW);
    const int p0 = pg % (HH * WW);
    #pragma unroll
    for (int r = 0; r < 16; r++) {
        int idx = t + r * 128;
        int cl = idx >> 5, pl = idx & 31;
        s[cl * 33 + pl] = x[((size_t)(b * C_IN) + c0 + cl) * (HH * WW) + p0 + pl];
    }
    __syncthreads();
    #pragma unroll
    for (int r = 0; r < 16; r++) {
        int idx = t + r * 128;
        int pl = idx >> 6, cl = idx & 63;
        int px = p0 + pl;
        int hs = px / WW, ws = px % WW;
        g_xT[((size_t)(b * HPAD + hs + 2) * HPAD + (ws + 2)) * C_IN + c0 + cl] =
            s[cl * 33 + pl];
    }
}

// ---------------- stage A: 1x1 compress GEMM ----------------
// 200 blocks x 128 threads. Block = 16 px x 64 outputs, K chunked by 64.
// Thread (px = t&15, og = t>>4): 8 consecutive outputs for one pixel.
#define AW_STRIDE 68
#define AX_STRIDE 20

__global__ void __launch_bounds__(128) stageA_compress(const float* __restrict__ x) {
    __shared__ float w_s[64 * AW_STRIDE];   // [c_local][o]
    __shared__ float x_s[64 * AX_STRIDE];   // [c_local][px]

    const int t   = threadIdx.x;
    const int g   = blockIdx.x * 16;        // global pixel (incl batch), 16-aligned
    const int b   = g / (HH * WW);
    const int p   = g % (HH * WW);

    const int px = t & 15;
    const int o0 = (t >> 4) << 3;           // 8 consecutive outputs

    u64 acc0 = 0, acc1 = 0, acc2 = 0, acc3 = 0;

    for (int c0 = 0; c0 < C_IN; c0 += 64) {
        __syncthreads();
        // weights chunk: 64 rows x 64 cols, float4 staging (1024 f4 / 128 thr = 8 each)
        #pragma unroll
        for (int r = 0; r < 8; r++) {
            int idx = t + r * 128;
            int row = idx >> 4, col4 = idx & 15;
            *(float4*)&w_s[row * AW_STRIDE + col4 * 4] =
                *(const float4*)&g_wc[(c0 + row) * CMID + col4 * 4];
        }
        // x chunk: 64 rows x 16 px (256 f4 / 128 thr = 2 each)
        #pragma unroll
        for (int r = 0; r < 2; r++) {
            int idx = t + r * 128;
            int row = idx >> 2, col4 = idx & 3;
            *(float4*)&x_s[row * AX_STRIDE + col4 * 4] =
                *(const float4*)&x[((size_t)(b * C_IN) + c0 + row) * (HH * WW) + p + col4 * 4];
        }
        __syncthreads();
        #pragma unroll 8
        for (int c = 0; c < 64; c++) {
            u64 xx = dup2f(x_s[c * AX_STRIDE + px]);
            ulonglong2 wA = *(const ulonglong2*)&w_s[c * AW_STRIDE + o0];
            ulonglong2 wB = *(const ulonglong2*)&w_s[c * AW_STRIDE + o0 + 4];
            fma2(acc0, xx, wA.x); fma2(acc1, xx, wA.y);
            fma2(acc2, xx, wB.x); fma2(acc3, xx, wB.y);
        }
    }

    const int pix = p + px;
    const int hs = pix / WW, ws = pix % WW;
    float* dst = &g_comp[((size_t)(b * CPH + hs + 1) * CPH + (ws + 1)) * CMID + o0];
    *(ulonglong2*)(dst)     = make_ulonglong2(acc0, acc1);
    *(ulonglong2*)(dst + 4) = make_ulonglong2(acc2, acc3);
}

// ---------------- stage B: 3x3 encoder conv (64 -> 100 ch) ----------------
#define CS_STRIDE 66
#define B_WBUF    (CMID * CK)                 // 6400 floats per tap
#define SMEM_B_BYTES ((2 * B_WBUF + 48 * CS_STRIDE) * (int)sizeof(float))

__global__ void __launch_bounds__(128) stageB_encoder() {
    extern __shared__ float smB[];
    float* wbuf   = smB;                       // [2][6400]
    float* comp_s = smB + 2 * B_WBUF;          // [48 px][66]

    const int t   = threadIdx.x;
    const int blk = blockIdx.x;
    const int b   = blk / 80;
    const int rem = blk % 80;
    const int h0  = (rem / 4) * 2;
    const int ws0 = (rem % 4) * 10;

    for (int i = t; i < 48 * CMID; i += 128) {
        int pxl = i >> 6, ci = i & 63;
        comp_s[pxl * CS_STRIDE + ci] =
            g_comp[((size_t)(b * CPH + h0 + pxl / 12) * CPH + ws0 + pxl % 12) * CMID + ci];
    }

    for (int i = t; i < B_WBUF / 4; i += 128)
        __pipeline_memcpy_async(&wbuf[i * 4], &g_wt[i * 4], 16);
    __pipeline_commit();

    const int og  = t / 5;          // 0..24 (t<125 active)
    const int pxg = t % 5;
    const bool active = (t < 125);

    u64 a00 = 0, a01 = 0, a10 = 0, a11 = 0;
    u64 b00 = 0, b01 = 0, b10 = 0, b11 = 0;

    for (int tap = 0; tap < 9; tap++) {
        if (tap < 8) {
            float* dst = &wbuf[((tap + 1) & 1) * B_WBUF];
            const float* src = &g_wt[(tap + 1) * B_WBUF];
            for (int i = t; i < B_WBUF / 4; i += 128)
                __pipeline_memcpy_async(&dst[i * 4], &src[i * 4], 16);
            __pipeline_commit();
            __pipeline_wait_prior(1);
        } else {
            __pipeline_wait_prior(0);
        }
        __syncthreads();

        if (active) {
            const float* ws = &wbuf[(tap & 1) * B_WBUF];
            const int dh = tap / 3, dw = tap % 3;
            const float* p00 = &comp_s[(dh * 12 + 2 * pxg + dw) * CS_STRIDE];
            const float* p01 = p00 + CS_STRIDE;
            const float* p10 = p00 + 12 * CS_STRIDE;
            const float* p11 = p10 + CS_STRIDE;
            #pragma unroll 8
            for (int ci = 0; ci < CMID; ci += 2) {
                float2 x00 = *(const float2*)&p00[ci];
                float2 x01 = *(const float2*)&p01[ci];
                float2 x10 = *(const float2*)&p10[ci];
                float2 x11 = *(const float2*)&p11[ci];
                ulonglong2 w0 = *(const ulonglong2*)&ws[ci * CK + og * 4];
                ulonglong2 w1 = *(const ulonglong2*)&ws[(ci + 1) * CK + og * 4];
                u64 d;
                d = dup2f(x00.x); fma2(a00, d, w0.x); fma2(a01, d, w0.y);
                d = dup2f(x01.x); fma2(a10, d, w0.x); fma2(a11, d, w0.y);
                d = dup2f(x10.x); fma2(b00, d, w0.x); fma2(b01, d, w0.y);
                d = dup2f(x11.x); fma2(b10, d, w0.x); fma2(b11, d, w0.y);
                d = dup2f(x00.y); fma2(a00, d, w1.x); fma2(a01, d, w1.y);
                d = dup2f(x01.y); fma2(a10, d, w1.x); fma2(a11, d, w1.y);
                d = dup2f(x10.y); fma2(b00, d, w1.x); fma2(b01, d, w1.y);
                d = dup2f(x11.y); fma2(b10, d, w1.x); fma2(b11, d, w1.y);
            }
        }
        __syncthreads();
    }

    if (active) {
        const int c0 = ws0 + 2 * pxg;
        float* r0 = &g_kern[((size_t)(b * HH + h0) * WW + c0) * CK + og * 4];
        float* r1 = &g_kern[((size_t)(b * HH + h0 + 1) * WW + c0) * CK + og * 4];
        *(ulonglong2*)(r0)      = make_ulonglong2(a00, a01);
        *(ulonglong2*)(r0 + CK) = make_ulonglong2(a10, a11);
        *(ulonglong2*)(r1)      = make_ulonglong2(b00, b01);
        *(ulonglong2*)(r1 + CK) = make_ulonglong2(b10, b11);
    }
}

// ---------------- stage C: pixel-shuffle + softmax + reassembly ----------------
// 1600 blocks x 512 threads: 2 src pixels per block, 1 channel per thread.
__global__ void __launch_bounds__(512) stageC_reassemble(float* __restrict__ out) {
    __shared__ float4 sk[2][KK];   // [px_in_block][k] = softmax weights for d=0..3

    const int t   = threadIdx.x;
    const int blk = blockIdx.x;
    const int b   = blk / 800;
    const int q   = blk % 800;

    const int wid = t >> 5, lane = t & 31;
    if (wid < 8) {   // 8 warps = 2 pixels x 4 subpixels
        const int px = wid >> 2, d = wid & 3;
        const int p  = 2 * q + px;
        const int hu = p / 20, pm20 = p % 20;
        const int hc = hu >> 1, sh = hu & 1;
        const int wc = 2 * pm20 + (d >> 1), sw = d & 1;
        float v = -3.0e38f;
        if (lane < KK)
            v = g_kern[((size_t)(b * HH + hc) * WW + wc) * CK + lane * 4 + sh * 2 + sw];
        float m = v;
        #pragma unroll
        for (int off = 16; off; off >>= 1)
            m = fmaxf(m, __shfl_xor_sync(0xffffffffu, m, off));
        float e = (lane < KK) ? __expf(v - m) : 0.f;
        float s = e;
        #pragma unroll
        for (int off = 16; off; off >>= 1)
            s += __shfl_xor_sync(0xffffffffu, s, off);
        if (lane < KK)
            ((float*)&sk[px][lane])[d] = e / s;
    }
    __syncthreads();

    const int half = t >> 8;           // which of the 2 pixels
    const int ch   = t & 255;          // channel
    const int p    = 2 * q + half;
    const int hsrc = p / WW, wsrc = p % WW;
    const int hu   = p / 20;
    const int wu0  = (p % 20) * 4;

    const float* xb = &g_xT[((size_t)(b * HPAD + hsrc) * HPAD + wsrc) * C_IN + ch];
    const ulonglong2* skp = (const ulonglong2*)&sk[half][0];

    u64 a01 = 0, a23 = 0;
    #pragma unroll
    for (int ki = 0; ki < 5; ki++) {
        float xr[5];
        #pragma unroll
        for (int kj = 0; kj < 5; kj++)
            xr[kj] = xb[(ki * HPAD + kj) * C_IN];
        #pragma unroll
        for (int kj = 0; kj < 5; kj++) {
            ulonglong2 w = skp[ki * 5 + kj];
            u64 xx = dup2f(xr[kj]);
            fma2(a01, xx, w.x);
            fma2(a23, xx, w.y);
        }
    }
    float* dst = out + ((size_t)(b * C_IN + ch) * (2 * HH) + hu) * (2 * WW) + wu0;
    *(ulonglong2*)dst = make_ulonglong2(a01, a23);
}

// ---------------- launch ----------------
extern "C" void kernel_launch(void* const* d_in, const int* in_sizes, int n_in,
                              void* d_out, int out_size) {
    const float* x     = (const float*)d_in[0];
    const float* wcomp = (const float*)d_in[1];
    const float* wenc  = (const float*)d_in[2];
    float* out = (float*)d_out;

    cudaFuncSetAttribute(stageB_encoder,
                         cudaFuncAttributeMaxDynamicSharedMemorySize, SMEM_B_BYTES);

    prep_kernel<<<(C_IN * CMID + 9 * CMID * CK + 255) / 256, 256>>>(wcomp, wenc);
    xpose_kernel<<<400, 128>>>(x);
    stageA_compress<<<200, 128>>>(x);
    stageB_encoder<<<160, 128, SMEM_B_BYTES>>>();
    stageC_reassemble<<<BATCH * 800, 512>>>(out);
}